// round 16
// baseline (speedup 1.0000x reference)
#include <cuda_runtime.h>
#include <cuda_fp16.h>
#include <math.h>
#include <stdint.h>

#define BATCH 128
#define TLEN  1024
#define NCH   64

// Activations: f (residual stream, fp16) and h (layer-0/1 intermediate, fp16). bss.
static __device__ __half g_f[BATCH * TLEN * NCH];
static __device__ __half g_h[BATCH * TLEN * NCH];
// Repacked fp16 B-fragments: 9 heavy sets x 3072 + conv0 set x 3072 uint2.
static __device__ __align__(16) uint2 g_wp[10 * 3072];

// ---------------------------------------------------------------------------
// helpers
// ---------------------------------------------------------------------------
__device__ __forceinline__ uint32_t smem_u32(const void* p) {
    uint32_t a;
    asm("{ .reg .u64 t; cvta.to.shared.u64 t, %1; cvt.u32.u64 %0, t; }" : "=r"(a) : "l"(p));
    return a;
}
__device__ __forceinline__ uint32_t h2pack(float lo, float hi) {
    __half2 h = __floats2half2_rn(lo, hi);
    return *(uint32_t*)&h;
}
__device__ __forceinline__ float2 h2unpack(uint32_t u) {
    __half2 h = *(__half2*)&u;
    return __half22float2(h);
}
__device__ __forceinline__ void mma_f16(float (&d)[4], const uint32_t (&a)[4], uint2 b) {
    asm volatile(
        "mma.sync.aligned.m16n8k16.row.col.f32.f16.f16.f32 "
        "{%0,%1,%2,%3}, {%4,%5,%6,%7}, {%8,%9}, {%0,%1,%2,%3};"
        : "+f"(d[0]), "+f"(d[1]), "+f"(d[2]), "+f"(d[3])
        : "r"(a[0]), "r"(a[1]), "r"(a[2]), "r"(a[3]), "r"(b.x), "r"(b.y));
}
#define LDSM4(r, a) \
    asm volatile("ldmatrix.sync.aligned.m8n8.x4.shared.b16 {%0,%1,%2,%3}, [%4];" \
        : "=r"((r)[0]), "=r"((r)[1]), "=r"((r)[2]), "=r"((r)[3]) : "r"(a))

__device__ __forceinline__ float softplusf(float x) {
    if (x > 20.f) return x;
    return log1pf(expf(x));
}

// ---------------------------------------------------------------------------
// Weight repack (fp16 B fragments for m16n8k16). Identical to round 5.
// ---------------------------------------------------------------------------
__global__ void repack_kernel(const float* __restrict__ w0b,
                              const float* __restrict__ wa,
                              const float* __restrict__ wb,
                              const float* __restrict__ w0a,
                              const float* __restrict__ w0r) {
    const int i = blockIdx.x * 256 + threadIdx.x;
    if (i >= 10 * 3072) return;
    const int lane = i & 31, tg = lane & 3;
    uint2 v;
    if (i < 9 * 3072) {
        const int s = i / 3072, r = i - s * 3072;
        const int t1 = r >> 5, ob8 = t1 & 7, kk = t1 >> 3;
        const int tap = kk >> 2, cc = kk & 3;
        const int o = ob8 * 8 + ((r & 31) >> 2);
        const int i0 = cc * 16 + 2 * tg;
        const float* src = (s == 0) ? w0b : (s <= 4 ? wa + (s - 1) * 12288 : wb + (s - 5) * 12288);
        v.x = h2pack(__ldg(src + (o * 64 + i0) * 3 + tap),     __ldg(src + (o * 64 + i0 + 1) * 3 + tap));
        v.y = h2pack(__ldg(src + (o * 64 + i0 + 8) * 3 + tap), __ldg(src + (o * 64 + i0 + 9) * 3 + tap));
    } else {
        const int r = i - 9 * 3072;
        const int t1 = r >> 5, ob8 = t1 & 15, kk = t1 >> 4;
        const int tap = kk >> 1, cc = kk & 1;
        const int o = ob8 * 8 + ((r & 31) >> 2);
        const int i0 = cc * 16 + 2 * tg;
        float f[4];
#pragma unroll
        for (int j = 0; j < 4; j++) {
            const int ii = i0 + (j >> 1) * 8 + (j & 1);
            float w = 0.f;
            if (ii < 23) {
                if (o < 64)            w = __ldg(w0a + (o * 23 + ii) * 3 + tap);
                else if (tap == 2)     w = __ldg(w0r + (o - 64) * 23 + ii);
            }
            f[j] = w;
        }
        v.x = h2pack(f[0], f[1]);
        v.y = h2pack(f[2], f[3]);
    }
    g_wp[i] = v;
}

// ---------------------------------------------------------------------------
// Unfused heavy conv (used only for the w0b / D=1 layer): round-15 version.
// RES=true: in = h, out = f (relu(conv)+resid, fp16).
// ---------------------------------------------------------------------------
#define MCONV_SMEM 36864

template <int D, bool RES>
__global__ void __launch_bounds__(256, 3) mconv_kernel(
    const __half* __restrict__ in,
    __half* __restrict__ out,
    const uint2* __restrict__ wp,
    const float* __restrict__ bias,
    int b0)
{
    extern __shared__ __align__(16) char smraw[];
    float* smf = (float*)smraw;
    constexpr int NR = 128 + 2 * D;
    const int tid = threadIdx.x;
    const int t0  = blockIdx.x * 128;
    const int b   = blockIdx.y + b0;

    {
        const __half* ib = in + ((size_t)b * TLEN + t0 - 2 * D) * 64;
        for (int idx = tid; idx < NR * 8; idx += 256) {
            const int r = idx >> 3, c8 = idx & 7;
            uint4 u = make_uint4(0, 0, 0, 0);
            if (t0 - 2 * D + r >= 0)
                u = __ldg((const uint4*)(ib + (size_t)r * 64) + c8);
            *(uint4*)(smraw + r * 144 + c8 * 16) = u;
        }
    }
    __syncthreads();

    const int lane = tid & 31, wid = tid >> 5;
    const int warpM = wid & 3, warpN = wid >> 2;
    const int g = lane >> 2, tg = lane & 3;

    const uint32_t a_base = smem_u32(smraw) +
        (warpM * 32 + (lane & 15)) * 144 + ((lane >> 4) << 4);
    const uint2* wl = wp + warpN * 128 + lane;

    float acc[2][4][4];
#pragma unroll
    for (int mf = 0; mf < 2; mf++)
#pragma unroll
        for (int nf = 0; nf < 4; nf++)
#pragma unroll
            for (int r = 0; r < 4; r++) acc[mf][nf][r] = 0.f;

    uint32_t Ab[2][2][4];
    uint2    Bb[2][4];
#define M_LOADA(buf, it) do {                                                  \
        const uint32_t ad_ = a_base + ((it) >> 2) * (D * 144) + ((it) & 3) * 32; \
        LDSM4(Ab[buf][0], ad_);                                                \
        LDSM4(Ab[buf][1], ad_ + 16 * 144);                                     \
    } while (0)
#define M_LOADB(buf, it) do {                                                  \
        const uint2* wk_ = wl + (it) * 256;                                    \
        Bb[buf][0] = __ldg(wk_);                                               \
        Bb[buf][1] = __ldg(wk_ + 32);                                          \
        Bb[buf][2] = __ldg(wk_ + 64);                                          \
        Bb[buf][3] = __ldg(wk_ + 96);                                          \
    } while (0)

    M_LOADB(0, 0);
    M_LOADA(0, 0);
#pragma unroll
    for (int it = 0; it < 12; it++) {
        const int cur = it & 1, nxt = cur ^ 1;
        if (it < 11) {
            M_LOADB(nxt, it + 1);
            M_LOADA(nxt, it + 1);
        }
        mma_f16(acc[0][0], Ab[cur][0], Bb[cur][0]);
        mma_f16(acc[0][1], Ab[cur][0], Bb[cur][1]);
        mma_f16(acc[0][2], Ab[cur][0], Bb[cur][2]);
        mma_f16(acc[0][3], Ab[cur][0], Bb[cur][3]);
        mma_f16(acc[1][0], Ab[cur][1], Bb[cur][0]);
        mma_f16(acc[1][1], Ab[cur][1], Bb[cur][1]);
        mma_f16(acc[1][2], Ab[cur][1], Bb[cur][2]);
        mma_f16(acc[1][3], Ab[cur][1], Bb[cur][3]);
    }
#undef M_LOADA
#undef M_LOADB

    __syncthreads();
#pragma unroll
    for (int mf = 0; mf < 2; mf++)
#pragma unroll
        for (int nf = 0; nf < 4; nf++) {
            const int ro = warpM * 32 + mf * 16 + g;
            const int co = warpN * 36 + nf * 8 + tg * 2;
            smf[ro * 72 + co]           = acc[mf][nf][0];
            smf[ro * 72 + co + 1]       = acc[mf][nf][1];
            smf[(ro + 8) * 72 + co]     = acc[mf][nf][2];
            smf[(ro + 8) * 72 + co + 1] = acc[mf][nf][3];
        }
    __syncthreads();

    const int tl = tid >> 1, h2 = tid & 1;
    const float* crow = smf + tl * 72 + h2 * 36;
    __half* orow = out + ((size_t)b * TLEN + t0 + tl) * 64 + h2 * 32;
    if (RES) {
#pragma unroll
        for (int j = 0; j < 8; j++) {
            const float4 bv = __ldg((const float4*)bias + h2 * 8 + j);
            const float4 c = *(const float4*)(crow + j * 4);
            const uint2 ru = __ldg((const uint2*)orow + j);
            const float2 r0 = h2unpack(ru.x);
            const float2 r1 = h2unpack(ru.y);
            uint2 u;
            u.x = h2pack(fmaxf(c.x + bv.x, 0.f) + r0.x,
                         fmaxf(c.y + bv.y, 0.f) + r0.y);
            u.y = h2pack(fmaxf(c.z + bv.z, 0.f) + r1.x,
                         fmaxf(c.w + bv.w, 0.f) + r1.y);
            ((uint2*)orow)[j] = u;
        }
    } else {
#pragma unroll
        for (int j = 0; j < 8; j++) {
            const float4 bv = __ldg((const float4*)bias + h2 * 8 + j);
            const float4 c = *(const float4*)(crow + j * 4);
            uint2 u;
            u.x = h2pack(fmaxf(c.x + bv.x, 0.f), fmaxf(c.y + bv.y, 0.f));
            u.y = h2pack(fmaxf(c.z + bv.z, 0.f), fmaxf(c.w + bv.w, 0.f));
            ((uint2*)orow)[j] = u;
        }
    }
}

// ---------------------------------------------------------------------------
// Fused residual block (all-fp16):
//   h = relu(ba + conv3(f, wa; D))   [smem only, fp16, zeroed t<0]
//   f = f + relu(bb + conv3(h, wb; D))      (HEAD: head outputs instead)
// smem: A1 (NR1 rows x 144B) | H (RH rows x 144B); fp32 bounce overlays later.
// ---------------------------------------------------------------------------
template <int D, bool HEAD>
__global__ void __launch_bounds__(256, 3) block_kernel(
    __half* __restrict__ f,
    const uint2* __restrict__ wpa, const uint2* __restrict__ wpb,
    const float* __restrict__ ba_, const float* __restrict__ bb_,
    int b0,
    const float* __restrict__ pet_w, const float* __restrict__ pet_b,
    const float* __restrict__ pck_w, const float* __restrict__ pck_b,
    const float* __restrict__ aet_w, const float* __restrict__ aet_b,
    float* __restrict__ hout)
{
    constexpr int HALO2 = (D == 16) ? 32 : 16;
    constexpr int RH    = 128 + HALO2;
    constexpr int NR1   = RH + 2 * D;
    constexpr int A1SZ  = NR1 * 144;
    extern __shared__ __align__(16) char sm[];
    float* smf = (float*)sm;
    char*  Hc  = sm + A1SZ;

    const int tid = threadIdx.x;
    const int t0  = blockIdx.x * 128;
    const int b   = blockIdx.y + b0;
    const int tbase = t0 - HALO2 - 2 * D;

    // ---- stage f rows tbase .. t0+127 (fp16 uint4 stream) ----
    {
        const __half* ib = f + ((size_t)b * TLEN + tbase) * 64;
        for (int idx = tid; idx < NR1 * 8; idx += 256) {
            const int r = idx >> 3, c8 = idx & 7;
            uint4 u = make_uint4(0, 0, 0, 0);
            if (tbase + r >= 0)
                u = __ldg((const uint4*)(ib + (size_t)r * 64) + c8);
            *(uint4*)(sm + r * 144 + c8 * 16) = u;
        }
    }
    __syncthreads();

    const int lane = tid & 31, wid = tid >> 5;
    const int warpM = wid & 3, warpN = wid >> 2;
    const int g = lane >> 2, tg = lane & 3;
    const uint32_t a1_lane = smem_u32(sm) + (lane & 15) * 144 + ((lane >> 4) << 4);
    const uint2* wla = wpa + warpN * 128 + lane;

    // ---- conv-a: RH/16 m-frags, strided over warpM; h -> smem ----
    for (int mi = warpM; mi < RH / 16; mi += 4) {
        float acc[4][4];
#pragma unroll
        for (int nf = 0; nf < 4; nf++)
#pragma unroll
            for (int r = 0; r < 4; r++) acc[nf][r] = 0.f;

        const uint32_t abase = a1_lane + mi * (16 * 144);
        uint32_t Aa[2][4];
        uint2    Ba[2][4];
#define A_LOADA(buf, it) \
        LDSM4(Aa[buf], abase + ((it) >> 2) * (D * 144) + ((it) & 3) * 32)
#define A_LOADB(buf, it) do {                                                  \
            const uint2* wk_ = wla + (it) * 256;                               \
            Ba[buf][0] = __ldg(wk_);                                           \
            Ba[buf][1] = __ldg(wk_ + 32);                                      \
            Ba[buf][2] = __ldg(wk_ + 64);                                      \
            Ba[buf][3] = __ldg(wk_ + 96);                                      \
        } while (0)
        A_LOADB(0, 0);
        A_LOADA(0, 0);
#pragma unroll
        for (int it = 0; it < 12; it++) {
            const int cur = it & 1, nxt = cur ^ 1;
            if (it < 11) {
                A_LOADB(nxt, it + 1);
                A_LOADA(nxt, it + 1);
            }
            mma_f16(acc[0], Aa[cur], Ba[cur][0]);
            mma_f16(acc[1], Aa[cur], Ba[cur][1]);
            mma_f16(acc[2], Aa[cur], Ba[cur][2]);
            mma_f16(acc[3], Aa[cur], Ba[cur][3]);
        }
#undef A_LOADA
#undef A_LOADB

        const int hr = mi * 16;
        const int t1g = t0 - HALO2 + hr + g;
#pragma unroll
        for (int nf = 0; nf < 4; nf++) {
            const int co = warpN * 32 + nf * 8 + tg * 2;
            const float bz0 = __ldg(ba_ + co), bz1 = __ldg(ba_ + co + 1);
            const uint32_t u0 = (t1g >= 0)
                ? h2pack(fmaxf(acc[nf][0] + bz0, 0.f), fmaxf(acc[nf][1] + bz1, 0.f)) : 0u;
            const uint32_t u1 = (t1g + 8 >= 0)
                ? h2pack(fmaxf(acc[nf][2] + bz0, 0.f), fmaxf(acc[nf][3] + bz1, 0.f)) : 0u;
            *(uint32_t*)(Hc + (hr + g) * 144 + co * 2)     = u0;
            *(uint32_t*)(Hc + (hr + 8 + g) * 144 + co * 2) = u1;
        }
    }
    __syncthreads();

    // ---- conv-b: 128 out rows from H (pipelined) ----
    const uint32_t h_lane = smem_u32(Hc) + (HALO2 - 2 * D) * 144 +
        (warpM * 32 + (lane & 15)) * 144 + ((lane >> 4) << 4);
    const uint2* wlb = wpb + warpN * 128 + lane;

    float acc[2][4][4];
#pragma unroll
    for (int mf = 0; mf < 2; mf++)
#pragma unroll
        for (int nf = 0; nf < 4; nf++)
#pragma unroll
            for (int r = 0; r < 4; r++) acc[mf][nf][r] = 0.f;

    uint32_t Bab[2][2][4];
    uint2    Bbb[2][4];
#define B_LOADA(buf, it) do {                                                  \
        const uint32_t ad_ = h_lane + ((it) >> 2) * (D * 144) + ((it) & 3) * 32; \
        LDSM4(Bab[buf][0], ad_);                                               \
        LDSM4(Bab[buf][1], ad_ + 16 * 144);                                    \
    } while (0)
#define B_LOADB(buf, it) do {                                                  \
        const uint2* wk_ = wlb + (it) * 256;                                   \
        Bbb[buf][0] = __ldg(wk_);                                              \
        Bbb[buf][1] = __ldg(wk_ + 32);                                         \
        Bbb[buf][2] = __ldg(wk_ + 64);                                         \
        Bbb[buf][3] = __ldg(wk_ + 96);                                         \
    } while (0)
    B_LOADB(0, 0);
    B_LOADA(0, 0);
#pragma unroll
    for (int it = 0; it < 12; it++) {
        const int cur = it & 1, nxt = cur ^ 1;
        if (it < 11) {
            B_LOADB(nxt, it + 1);
            B_LOADA(nxt, it + 1);
        }
        mma_f16(acc[0][0], Bab[cur][0], Bbb[cur][0]);
        mma_f16(acc[0][1], Bab[cur][0], Bbb[cur][1]);
        mma_f16(acc[0][2], Bab[cur][0], Bbb[cur][2]);
        mma_f16(acc[0][3], Bab[cur][0], Bbb[cur][3]);
        mma_f16(acc[1][0], Bab[cur][1], Bbb[cur][0]);
        mma_f16(acc[1][1], Bab[cur][1], Bbb[cur][1]);
        mma_f16(acc[1][2], Bab[cur][1], Bbb[cur][2]);
        mma_f16(acc[1][3], Bab[cur][1], Bbb[cur][3]);
    }
#undef B_LOADA
#undef B_LOADB
    __syncthreads();   // all A1/H reads done -> overlay bounce

#pragma unroll
    for (int mf = 0; mf < 2; mf++)
#pragma unroll
        for (int nf = 0; nf < 4; nf++) {
            const int ro = warpM * 32 + mf * 16 + g;
            const int co = warpN * 36 + nf * 8 + tg * 2;
            smf[ro * 72 + co]           = acc[mf][nf][0];
            smf[ro * 72 + co + 1]       = acc[mf][nf][1];
            smf[(ro + 8) * 72 + co]     = acc[mf][nf][2];
            smf[(ro + 8) * 72 + co + 1] = acc[mf][nf][3];
        }
    __syncthreads();

    const int tl = tid >> 1, h2 = tid & 1;
    const float* crow = smf + tl * 72 + h2 * 36;
    __half* orow = f + ((size_t)b * TLEN + t0 + tl) * 64 + h2 * 32;
    if (HEAD) {
        float a0 = 0.f, a1 = 0.f, a2 = 0.f;
#pragma unroll
        for (int j = 0; j < 8; j++) {
            const float4 bv = __ldg((const float4*)bb_ + h2 * 8 + j);
            const float4 c = *(const float4*)(crow + j * 4);
            const uint2 ru = __ldg((const uint2*)orow + j);
            const float2 r0 = h2unpack(ru.x);
            const float2 r1 = h2unpack(ru.y);
            float4 v;
            v.x = fmaxf(c.x + bv.x, 0.f) + r0.x;
            v.y = fmaxf(c.y + bv.y, 0.f) + r0.y;
            v.z = fmaxf(c.z + bv.z, 0.f) + r1.x;
            v.w = fmaxf(c.w + bv.w, 0.f) + r1.y;
            const float4 w0 = __ldg((const float4*)pet_w + h2 * 8 + j);
            const float4 w1 = __ldg((const float4*)pck_w + h2 * 8 + j);
            const float4 w2 = __ldg((const float4*)aet_w + h2 * 8 + j);
            a0 += v.x * w0.x + v.y * w0.y + v.z * w0.z + v.w * w0.w;
            a1 += v.x * w1.x + v.y * w1.y + v.z * w1.z + v.w * w1.w;
            a2 += v.x * w2.x + v.y * w2.y + v.z * w2.z + v.w * w2.w;
        }
        a0 += __shfl_xor_sync(0xFFFFFFFFu, a0, 1);
        a1 += __shfl_xor_sync(0xFFFFFFFFu, a1, 1);
        a2 += __shfl_xor_sync(0xFFFFFFFFu, a2, 1);
        const float pet = softplusf(a0 + __ldg(pet_b));
        const float pck = softplusf(a1 + __ldg(pck_b));
        const float z   = a2 + __ldg(aet_w + 64) * pet + __ldg(aet_w + 65) * pck + __ldg(aet_b);
        const float aet = pet / (1.f + expf(-z));
        const float cwd = pet - aet;
        const int N = BATCH * TLEN;
        const int gg = b * TLEN + t0 + tl;
        if (h2 == 0) {
            hout[gg]     = pet;
            hout[N + gg] = pck;
        } else {
            hout[2 * N + gg] = aet;
            hout[3 * N + gg] = cwd;
        }
    } else {
#pragma unroll
        for (int j = 0; j < 8; j++) {
            const float4 bv = __ldg((const float4*)bb_ + h2 * 8 + j);
            const float4 c = *(const float4*)(crow + j * 4);
            const uint2 ru = __ldg((const uint2*)orow + j);
            const float2 r0 = h2unpack(ru.x);
            const float2 r1 = h2unpack(ru.y);
            uint2 u;
            u.x = h2pack(fmaxf(c.x + bv.x, 0.f) + r0.x,
                         fmaxf(c.y + bv.y, 0.f) + r0.y);
            u.y = h2pack(fmaxf(c.z + bv.z, 0.f) + r1.x,
                         fmaxf(c.w + bv.w, 0.f) + r1.y);
            ((uint2*)orow)[j] = u;
        }
    }
}

// ---------------------------------------------------------------------------
// Fused layer-0: h = relu(conv3(xin,w0a)) [fp16]; f = conv1(xin,w0r) [fp16].
// ---------------------------------------------------------------------------
#define CONV0_SMEM 18432

__global__ void __launch_bounds__(256, 4) conv0_kernel(
    const float* __restrict__ x, const int* __restrict__ ids,
    const float* __restrict__ emb,
    const uint2* __restrict__ wp0,
    const float* __restrict__ b0a, const float* __restrict__ b0r,
    __half* __restrict__ hout, __half* __restrict__ fout,
    int bofs)
{
    extern __shared__ __align__(16) char smraw[];
    __half* smh = (__half*)smraw;
    float*  smf = (float*)smraw;
    const int tid = threadIdx.x;
    const int t0  = blockIdx.x * 64;
    const int b   = blockIdx.y + bofs;

    const int id = __ldg(ids + b);
    for (int idx = tid; idx < 32 * 66; idx += 256) {
        const int ch = idx / 66, r = idx - ch * 66;
        const int t = t0 - 2 + r;
        float v = 0.f;
        if (t >= 0) {
            if (ch < 15)       v = __ldg(x + ((size_t)b * 15 + ch) * TLEN + t);
            else if (ch < 23)  v = __ldg(emb + id * 8 + (ch - 15));
        }
        smh[r * 40 + ch] = __float2half_rn(v);
    }
    __syncthreads();

    const int lane = tid & 31, wid = tid >> 5;
    const int warpM = wid & 1, warpN = wid >> 1;
    const int g = lane >> 2, tg = lane & 3;

    const uint32_t a_base = smem_u32(smraw) +
        (warpM * 32 + (lane & 15)) * 80 + ((lane >> 4) << 4);
    const uint2* wl = wp0 + lane;

    float acc[2][4][4];
#pragma unroll
    for (int mf = 0; mf < 2; mf++)
#pragma unroll
        for (int nf = 0; nf < 4; nf++)
#pragma unroll
            for (int r = 0; r < 4; r++) acc[mf][nf][r] = 0.f;

#pragma unroll
    for (int kk = 0; kk < 6; kk++) {
        const int tap = kk >> 1, cc = kk & 1;
        uint32_t A0[4], A1[4];
        const uint32_t ad = a_base + tap * 80 + cc * 32;
        LDSM4(A0, ad);
        LDSM4(A1, ad + 16 * 80);
        const uint2* wk = wl + (kk * 16 + warpN * 4) * 32;
        const uint2 b0f = __ldg(wk);
        const uint2 b1f = __ldg(wk + 32);
        const uint2 b2f = __ldg(wk + 64);
        const uint2 b3f = __ldg(wk + 96);
        mma_f16(acc[0][0], A0, b0f);
        mma_f16(acc[0][1], A0, b1f);
        mma_f16(acc[0][2], A0, b2f);
        mma_f16(acc[0][3], A0, b3f);
        mma_f16(acc[1][0], A1, b0f);
        mma_f16(acc[1][1], A1, b1f);
        mma_f16(acc[1][2], A1, b2f);
        mma_f16(acc[1][3], A1, b3f);
    }
    __syncthreads();

    const int tl = tid >> 1, h2 = tid & 1;
    if (warpN < 2) {
#pragma unroll
        for (int mf = 0; mf < 2; mf++)
#pragma unroll
            for (int nf = 0; nf < 4; nf++) {
                const int ro = warpM * 32 + mf * 16 + g;
                const int co = warpN * 36 + nf * 8 + tg * 2;
                smf[ro * 72 + co]           = acc[mf][nf][0];
                smf[ro * 72 + co + 1]       = acc[mf][nf][1];
                smf[(ro + 8) * 72 + co]     = acc[mf][nf][2];
                smf[(ro + 8) * 72 + co + 1] = acc[mf][nf][3];
            }
    }
    __syncthreads();
    if (tid < 128) {
        const float* crow = smf + tl * 72 + h2 * 36;
        __half* orow = hout + ((size_t)b * TLEN + t0 + tl) * 64 + h2 * 32;
#pragma unroll
        for (int j = 0; j < 8; j++) {
            const float4 bv = __ldg((const float4*)b0a + h2 * 8 + j);
            const float4 c = *(const float4*)(crow + j * 4);
            uint2 u;
            u.x = h2pack(fmaxf(c.x + bv.x, 0.f), fmaxf(c.y + bv.y, 0.f));
            u.y = h2pack(fmaxf(c.z + bv.z, 0.f), fmaxf(c.w + bv.w, 0.f));
            ((uint2*)orow)[j] = u;
        }
    }
    __syncthreads();
    if (warpN >= 2) {
#pragma unroll
        for (int mf = 0; mf < 2; mf++)
#pragma unroll
            for (int nf = 0; nf < 4; nf++) {
                const int ro = warpM * 32 + mf * 16 + g;
                const int co = (warpN - 2) * 36 + nf * 8 + tg * 2;
                smf[ro * 72 + co]           = acc[mf][nf][0];
                smf[ro * 72 + co + 1]       = acc[mf][nf][1];
                smf[(ro + 8) * 72 + co]     = acc[mf][nf][2];
                smf[(ro + 8) * 72 + co + 1] = acc[mf][nf][3];
            }
    }
    __syncthreads();
    if (tid < 128) {
        const float* crow = smf + tl * 72 + h2 * 36;
        __half* orow = fout + ((size_t)b * TLEN + t0 + tl) * 64 + h2 * 32;
#pragma unroll
        for (int j = 0; j < 8; j++) {
            const float4 bv = __ldg((const float4*)b0r + h2 * 8 + j);
            const float4 c = *(const float4*)(crow + j * 4);
            uint2 u;
            u.x = h2pack(c.x + bv.x, c.y + bv.y);
            u.y = h2pack(c.z + bv.z, c.w + bv.w);
            ((uint2*)orow)[j] = u;
        }
    }
}

// ===========================================================================
#define NCHAIN 4
#define BCH    (BATCH / NCHAIN)   // 32 batches per chain

extern "C" void kernel_launch(void* const* d_in, const int* in_sizes, int n_in,
                              void* d_out, int out_size)
{
    const float* x     = (const float*)d_in[0];
    const int*   ids   = (const int*)  d_in[1];
    const float* emb   = (const float*)d_in[2];
    const float* w0a   = (const float*)d_in[3];
    const float* b0a   = (const float*)d_in[4];
    const float* w0b   = (const float*)d_in[5];
    const float* b0b   = (const float*)d_in[6];
    const float* w0r   = (const float*)d_in[7];
    const float* b0r   = (const float*)d_in[8];
    const float* wa    = (const float*)d_in[9];
    const float* ba    = (const float*)d_in[10];
    const float* wb    = (const float*)d_in[11];
    const float* bb    = (const float*)d_in[12];
    const float* pet_w = (const float*)d_in[13];
    const float* pet_b = (const float*)d_in[14];
    const float* pck_w = (const float*)d_in[15];
    const float* pck_b = (const float*)d_in[16];
    const float* aet_w = (const float*)d_in[17];
    const float* aet_b = (const float*)d_in[18];
    float* out = (float*)d_out;

    __half *f, *h; uint2* wp;
    cudaGetSymbolAddress((void**)&f,  g_f);
    cudaGetSymbolAddress((void**)&h,  g_h);
    cudaGetSymbolAddress((void**)&wp, g_wp);

    static cudaStream_t s_aux[NCHAIN - 1] = {};
    static cudaEvent_t  ev_fork = nullptr;
    static cudaEvent_t  ev_join[NCHAIN - 1] = {};
    if (ev_fork == nullptr) {
        for (int i = 0; i < NCHAIN - 1; i++)
            cudaStreamCreateWithFlags(&s_aux[i], cudaStreamNonBlocking);
        cudaEventCreateWithFlags(&ev_fork, cudaEventDisableTiming);
        for (int i = 0; i < NCHAIN - 1; i++)
            cudaEventCreateWithFlags(&ev_join[i], cudaEventDisableTiming);
        // raise dynamic smem limits for the fused blocks (one-time, idempotent)
        cudaFuncSetAttribute(block_kernel<2,  false>, cudaFuncAttributeMaxDynamicSharedMemorySize, 148 * 144 + 144 * 144);
        cudaFuncSetAttribute(block_kernel<4,  false>, cudaFuncAttributeMaxDynamicSharedMemorySize, 152 * 144 + 144 * 144);
        cudaFuncSetAttribute(block_kernel<8,  false>, cudaFuncAttributeMaxDynamicSharedMemorySize, 160 * 144 + 144 * 144);
        cudaFuncSetAttribute(block_kernel<16, true >, cudaFuncAttributeMaxDynamicSharedMemorySize, 192 * 144 + 160 * 144);
    }

    repack_kernel<<<(10 * 3072 + 255) / 256, 256>>>(w0b, wa, wb, w0a, w0r);
    cudaEventRecord(ev_fork, 0);
    for (int i = 0; i < NCHAIN - 1; i++)
        cudaStreamWaitEvent(s_aux[i], ev_fork, 0);

    const dim3 grid0(TLEN / 64, BCH);
    const dim3 grid(TLEN / 128, BCH);
    const int SM2  = 148 * 144 + 144 * 144;
    const int SM4  = 152 * 144 + 144 * 144;
    const int SM8  = 160 * 144 + 144 * 144;
    const int SM16 = 192 * 144 + 160 * 144;

    for (int c = 0; c < NCHAIN; c++) {
        cudaStream_t s = (c == 0) ? (cudaStream_t)0 : s_aux[c - 1];
        const int b0 = c * BCH;

        conv0_kernel<<<grid0, 256, CONV0_SMEM, s>>>(x, ids, emb, wp + 9 * 3072,
                                                    b0a, b0r, h, f, b0);
        mconv_kernel<1, true><<<grid, 256, MCONV_SMEM, s>>>(h, f, wp + 0 * 3072, b0b, b0);

        block_kernel<2,  false><<<grid, 256, SM2,  s>>>(f, wp + 1 * 3072, wp + 5 * 3072,
            ba + 0 * NCH, bb + 0 * NCH, b0, pet_w, pet_b, pck_w, pck_b, aet_w, aet_b, out);
        block_kernel<4,  false><<<grid, 256, SM4,  s>>>(f, wp + 2 * 3072, wp + 6 * 3072,
            ba + 1 * NCH, bb + 1 * NCH, b0, pet_w, pet_b, pck_w, pck_b, aet_w, aet_b, out);
        block_kernel<8,  false><<<grid, 256, SM8,  s>>>(f, wp + 3 * 3072, wp + 7 * 3072,
            ba + 2 * NCH, bb + 2 * NCH, b0, pet_w, pet_b, pck_w, pck_b, aet_w, aet_b, out);
        block_kernel<16, true ><<<grid, 256, SM16, s>>>(f, wp + 4 * 3072, wp + 8 * 3072,
            ba + 3 * NCH, bb + 3 * NCH, b0, pet_w, pet_b, pck_w, pck_b, aet_w, aet_b, out);
    }

    for (int i = 0; i < NCHAIN - 1; i++) {
        cudaEventRecord(ev_join[i], s_aux[i]);
        cudaStreamWaitEvent((cudaStream_t)0, ev_join[i], 0);
    }
}

// round 17
// speedup vs baseline: 1.1536x; 1.1536x over previous
#include <cuda_runtime.h>
#include <cuda_fp16.h>
#include <math.h>
#include <stdint.h>

#define BATCH 128
#define TLEN  1024
#define NCH   64

// Activations: f (residual stream, fp16) and h (conv intermediate, fp16). bss.
static __device__ __half g_f[BATCH * TLEN * NCH];
static __device__ __half g_h[BATCH * TLEN * NCH];
// Repacked fp16 B-fragments: 9 heavy sets x 3072 + conv0 set x 3072 uint2.
static __device__ __align__(16) uint2 g_wp[10 * 3072];

// ---------------------------------------------------------------------------
// helpers
// ---------------------------------------------------------------------------
__device__ __forceinline__ uint32_t smem_u32(const void* p) {
    uint32_t a;
    asm("{ .reg .u64 t; cvta.to.shared.u64 t, %1; cvt.u32.u64 %0, t; }" : "=r"(a) : "l"(p));
    return a;
}
__device__ __forceinline__ uint32_t h2pack(float lo, float hi) {
    __half2 h = __floats2half2_rn(lo, hi);
    return *(uint32_t*)&h;
}
__device__ __forceinline__ float2 h2unpack(uint32_t u) {
    __half2 h = *(__half2*)&u;
    return __half22float2(h);
}
__device__ __forceinline__ void mma_f16(float (&d)[4], const uint32_t (&a)[4], uint2 b) {
    asm volatile(
        "mma.sync.aligned.m16n8k16.row.col.f32.f16.f16.f32 "
        "{%0,%1,%2,%3}, {%4,%5,%6,%7}, {%8,%9}, {%0,%1,%2,%3};"
        : "+f"(d[0]), "+f"(d[1]), "+f"(d[2]), "+f"(d[3])
        : "r"(a[0]), "r"(a[1]), "r"(a[2]), "r"(a[3]), "r"(b.x), "r"(b.y));
}
#define LDSM4(r, a) \
    asm volatile("ldmatrix.sync.aligned.m8n8.x4.shared.b16 {%0,%1,%2,%3}, [%4];" \
        : "=r"((r)[0]), "=r"((r)[1]), "=r"((r)[2]), "=r"((r)[3]) : "r"(a))
#define CP_ASYNC16(dst, src, sz) \
    asm volatile("cp.async.ca.shared.global [%0], [%1], 16, %2;" \
        :: "r"(dst), "l"(src), "r"(sz) : "memory")
#define CP_COMMIT_WAIT() \
    asm volatile("cp.async.commit_group;\n\tcp.async.wait_group 0;" ::: "memory")

__device__ __forceinline__ float softplusf(float x) {
    if (x > 20.f) return x;
    return log1pf(expf(x));
}

// ---------------------------------------------------------------------------
// Weight repack (fp16 B fragments for m16n8k16). Identical to round 5.
// ---------------------------------------------------------------------------
__global__ void repack_kernel(const float* __restrict__ w0b,
                              const float* __restrict__ wa,
                              const float* __restrict__ wb,
                              const float* __restrict__ w0a,
                              const float* __restrict__ w0r) {
    const int i = blockIdx.x * 256 + threadIdx.x;
    if (i >= 10 * 3072) return;
    const int lane = i & 31, tg = lane & 3;
    uint2 v;
    if (i < 9 * 3072) {
        const int s = i / 3072, r = i - s * 3072;
        const int t1 = r >> 5, ob8 = t1 & 7, kk = t1 >> 3;
        const int tap = kk >> 2, cc = kk & 3;
        const int o = ob8 * 8 + ((r & 31) >> 2);
        const int i0 = cc * 16 + 2 * tg;
        const float* src = (s == 0) ? w0b : (s <= 4 ? wa + (s - 1) * 12288 : wb + (s - 5) * 12288);
        v.x = h2pack(__ldg(src + (o * 64 + i0) * 3 + tap),     __ldg(src + (o * 64 + i0 + 1) * 3 + tap));
        v.y = h2pack(__ldg(src + (o * 64 + i0 + 8) * 3 + tap), __ldg(src + (o * 64 + i0 + 9) * 3 + tap));
    } else {
        const int r = i - 9 * 3072;
        const int t1 = r >> 5, ob8 = t1 & 15, kk = t1 >> 4;
        const int tap = kk >> 1, cc = kk & 1;
        const int o = ob8 * 8 + ((r & 31) >> 2);
        const int i0 = cc * 16 + 2 * tg;
        float f[4];
#pragma unroll
        for (int j = 0; j < 4; j++) {
            const int ii = i0 + (j >> 1) * 8 + (j & 1);
            float w = 0.f;
            if (ii < 23) {
                if (o < 64)            w = __ldg(w0a + (o * 23 + ii) * 3 + tap);
                else if (tap == 2)     w = __ldg(w0r + (o - 64) * 23 + ii);
            }
            f[j] = w;
        }
        v.x = h2pack(f[0], f[1]);
        v.y = h2pack(f[2], f[3]);
    }
    g_wp[i] = v;
}

// ---------------------------------------------------------------------------
// Heavy conv 64->64 K=3, fp16 mma, channels-last; ALL activations fp16.
// Staging via cp.async zfill (bit-identical byte copy, no register roundtrip).
// RES=false: in = f, out = h (relu).
// RES=true, HEAD=false: in = h, out = f (relu(conv)+resid, fp16).
// RES=true, HEAD=true : in = h, resid = f (read-only); epilogue computes
//                       heads (pet,pck,aet,cwd) into 'hout' (fp32).
// ---------------------------------------------------------------------------
#define MCONV_SMEM 36864

template <int D, bool RES, bool HEAD>
__global__ void __launch_bounds__(256, 3) mconv_kernel(
    const __half* __restrict__ in,
    __half* __restrict__ out,           // h or f (HEAD: residual f, read-only)
    const uint2* __restrict__ wp,
    const float* __restrict__ bias,
    int b0,
    const float* __restrict__ pet_w, const float* __restrict__ pet_b,
    const float* __restrict__ pck_w, const float* __restrict__ pck_b,
    const float* __restrict__ aet_w, const float* __restrict__ aet_b,
    float* __restrict__ hout)           // HEAD: harness output
{
    extern __shared__ __align__(16) char smraw[];
    float* smf = (float*)smraw;
    constexpr int NR = 128 + 2 * D;
    const int tid = threadIdx.x;
    const int t0  = blockIdx.x * 128;
    const int b   = blockIdx.y + b0;

    // ---- stage A: fp16 rows via cp.async (zero-fill for t<0) ----
    {
        const __half* ib = in + ((size_t)b * TLEN + t0 - 2 * D) * 64;
        const uint32_t sbase = smem_u32(smraw);
        for (int idx = tid; idx < NR * 8; idx += 256) {
            const int r = idx >> 3, c8 = idx & 7;
            const int sz = (t0 - 2 * D + r >= 0) ? 16 : 0;
            CP_ASYNC16(sbase + r * 144 + c8 * 16,
                       (const void*)((const uint4*)(ib + (size_t)r * 64) + c8), sz);
        }
        CP_COMMIT_WAIT();
    }
    __syncthreads();

    const int lane = tid & 31, wid = tid >> 5;
    const int warpM = wid & 3, warpN = wid >> 2;
    const int g = lane >> 2, tg = lane & 3;

    const uint32_t a_base = smem_u32(smraw) +
        (warpM * 32 + (lane & 15)) * 144 + ((lane >> 4) << 4);
    const uint2* wl = wp + warpN * 128 + lane;

    float acc[2][4][4];
#pragma unroll
    for (int mf = 0; mf < 2; mf++)
#pragma unroll
        for (int nf = 0; nf < 4; nf++)
#pragma unroll
            for (int r = 0; r < 4; r++) acc[mf][nf][r] = 0.f;

    // ---- software-pipelined mainloop: 12 iters, double-buffered A/B frags ----
    uint32_t Ab[2][2][4];
    uint2    Bb[2][4];
#define LOADA(buf, it) do {                                                    \
        const uint32_t ad_ = a_base + ((it) >> 2) * (D * 144) + ((it) & 3) * 32; \
        LDSM4(Ab[buf][0], ad_);                                                \
        LDSM4(Ab[buf][1], ad_ + 16 * 144);                                     \
    } while (0)
#define LOADB(buf, it) do {                                                    \
        const uint2* wk_ = wl + (it) * 256;                                    \
        Bb[buf][0] = __ldg(wk_);                                               \
        Bb[buf][1] = __ldg(wk_ + 32);                                          \
        Bb[buf][2] = __ldg(wk_ + 64);                                          \
        Bb[buf][3] = __ldg(wk_ + 96);                                          \
    } while (0)

    LOADB(0, 0);
    LOADA(0, 0);
#pragma unroll
    for (int it = 0; it < 12; it++) {
        const int cur = it & 1, nxt = cur ^ 1;
        if (it < 11) {
            LOADB(nxt, it + 1);
            LOADA(nxt, it + 1);
        }
        mma_f16(acc[0][0], Ab[cur][0], Bb[cur][0]);
        mma_f16(acc[0][1], Ab[cur][0], Bb[cur][1]);
        mma_f16(acc[0][2], Ab[cur][0], Bb[cur][2]);
        mma_f16(acc[0][3], Ab[cur][0], Bb[cur][3]);
        mma_f16(acc[1][0], Ab[cur][1], Bb[cur][0]);
        mma_f16(acc[1][1], Ab[cur][1], Bb[cur][1]);
        mma_f16(acc[1][2], Ab[cur][1], Bb[cur][2]);
        mma_f16(acc[1][3], Ab[cur][1], Bb[cur][3]);
    }
#undef LOADA
#undef LOADB

    // ---- epilogue bounce (stride 72 words) ----
    __syncthreads();
#pragma unroll
    for (int mf = 0; mf < 2; mf++)
#pragma unroll
        for (int nf = 0; nf < 4; nf++) {
            const int ro = warpM * 32 + mf * 16 + g;
            const int co = warpN * 36 + nf * 8 + tg * 2;
            smf[ro * 72 + co]           = acc[mf][nf][0];
            smf[ro * 72 + co + 1]       = acc[mf][nf][1];
            smf[(ro + 8) * 72 + co]     = acc[mf][nf][2];
            smf[(ro + 8) * 72 + co + 1] = acc[mf][nf][3];
        }
    __syncthreads();

    const int tl = tid >> 1, h2 = tid & 1;
    const float* crow = smf + tl * 72 + h2 * 36;
    __half* orow = out + ((size_t)b * TLEN + t0 + tl) * 64 + h2 * 32;
    if (HEAD) {
        // residual f (fp16, read-only) -> head outputs
        float a0 = 0.f, a1 = 0.f, a2 = 0.f;
#pragma unroll
        for (int j = 0; j < 8; j++) {
            const float4 bv = __ldg((const float4*)bias + h2 * 8 + j);
            const float4 c = *(const float4*)(crow + j * 4);
            const uint2 ru = __ldg((const uint2*)orow + j);
            const float2 r0 = h2unpack(ru.x);
            const float2 r1 = h2unpack(ru.y);
            float4 v;
            v.x = fmaxf(c.x + bv.x, 0.f) + r0.x;
            v.y = fmaxf(c.y + bv.y, 0.f) + r0.y;
            v.z = fmaxf(c.z + bv.z, 0.f) + r1.x;
            v.w = fmaxf(c.w + bv.w, 0.f) + r1.y;
            const float4 w0 = __ldg((const float4*)pet_w + h2 * 8 + j);
            const float4 w1 = __ldg((const float4*)pck_w + h2 * 8 + j);
            const float4 w2 = __ldg((const float4*)aet_w + h2 * 8 + j);
            a0 += v.x * w0.x + v.y * w0.y + v.z * w0.z + v.w * w0.w;
            a1 += v.x * w1.x + v.y * w1.y + v.z * w1.z + v.w * w1.w;
            a2 += v.x * w2.x + v.y * w2.y + v.z * w2.z + v.w * w2.w;
        }
        a0 += __shfl_xor_sync(0xFFFFFFFFu, a0, 1);
        a1 += __shfl_xor_sync(0xFFFFFFFFu, a1, 1);
        a2 += __shfl_xor_sync(0xFFFFFFFFu, a2, 1);
        const float pet = softplusf(a0 + __ldg(pet_b));
        const float pck = softplusf(a1 + __ldg(pck_b));
        const float z   = a2 + __ldg(aet_w + 64) * pet + __ldg(aet_w + 65) * pck + __ldg(aet_b);
        const float aet = pet / (1.f + expf(-z));
        const float cwd = pet - aet;
        const int N = BATCH * TLEN;
        const int gg = b * TLEN + t0 + tl;
        if (h2 == 0) {
            hout[gg]     = pet;
            hout[N + gg] = pck;
        } else {
            hout[2 * N + gg] = aet;
            hout[3 * N + gg] = cwd;
        }
    } else if (RES) {
        // f = relu(conv + bias) + f   (fp16 residual stream)
#pragma unroll
        for (int j = 0; j < 8; j++) {
            const float4 bv = __ldg((const float4*)bias + h2 * 8 + j);
            const float4 c = *(const float4*)(crow + j * 4);
            const uint2 ru = __ldg((const uint2*)orow + j);
            const float2 r0 = h2unpack(ru.x);
            const float2 r1 = h2unpack(ru.y);
            uint2 u;
            u.x = h2pack(fmaxf(c.x + bv.x, 0.f) + r0.x,
                         fmaxf(c.y + bv.y, 0.f) + r0.y);
            u.y = h2pack(fmaxf(c.z + bv.z, 0.f) + r1.x,
                         fmaxf(c.w + bv.w, 0.f) + r1.y);
            ((uint2*)orow)[j] = u;
        }
    } else {
        // h = relu(conv + bias)  (fp16)
#pragma unroll
        for (int j = 0; j < 8; j++) {
            const float4 bv = __ldg((const float4*)bias + h2 * 8 + j);
            const float4 c = *(const float4*)(crow + j * 4);
            uint2 u;
            u.x = h2pack(fmaxf(c.x + bv.x, 0.f), fmaxf(c.y + bv.y, 0.f));
            u.y = h2pack(fmaxf(c.z + bv.z, 0.f), fmaxf(c.w + bv.w, 0.f));
            ((uint2*)orow)[j] = u;
        }
    }
}

// ---------------------------------------------------------------------------
// Fused layer-0: h = relu(conv3(xin,w0a)) [fp16]; f = conv1(xin,w0r) [fp16].
// ---------------------------------------------------------------------------
#define CONV0_SMEM 18432

__global__ void __launch_bounds__(256, 4) conv0_kernel(
    const float* __restrict__ x, const int* __restrict__ ids,
    const float* __restrict__ emb,
    const uint2* __restrict__ wp0,
    const float* __restrict__ b0a, const float* __restrict__ b0r,
    __half* __restrict__ hout, __half* __restrict__ fout,
    int bofs)
{
    extern __shared__ __align__(16) char smraw[];
    __half* smh = (__half*)smraw;
    float*  smf = (float*)smraw;
    const int tid = threadIdx.x;
    const int t0  = blockIdx.x * 64;
    const int b   = blockIdx.y + bofs;

    const int id = __ldg(ids + b);
    for (int idx = tid; idx < 32 * 66; idx += 256) {
        const int ch = idx / 66, r = idx - ch * 66;
        const int t = t0 - 2 + r;
        float v = 0.f;
        if (t >= 0) {
            if (ch < 15)       v = __ldg(x + ((size_t)b * 15 + ch) * TLEN + t);
            else if (ch < 23)  v = __ldg(emb + id * 8 + (ch - 15));
        }
        smh[r * 40 + ch] = __float2half_rn(v);
    }
    __syncthreads();

    const int lane = tid & 31, wid = tid >> 5;
    const int warpM = wid & 1, warpN = wid >> 1;
    const int g = lane >> 2, tg = lane & 3;

    const uint32_t a_base = smem_u32(smraw) +
        (warpM * 32 + (lane & 15)) * 80 + ((lane >> 4) << 4);
    const uint2* wl = wp0 + lane;

    float acc[2][4][4];
#pragma unroll
    for (int mf = 0; mf < 2; mf++)
#pragma unroll
        for (int nf = 0; nf < 4; nf++)
#pragma unroll
            for (int r = 0; r < 4; r++) acc[mf][nf][r] = 0.f;

#pragma unroll
    for (int kk = 0; kk < 6; kk++) {
        const int tap = kk >> 1, cc = kk & 1;
        uint32_t A0[4], A1[4];
        const uint32_t ad = a_base + tap * 80 + cc * 32;
        LDSM4(A0, ad);
        LDSM4(A1, ad + 16 * 80);
        const uint2* wk = wl + (kk * 16 + warpN * 4) * 32;
        const uint2 b0f = __ldg(wk);
        const uint2 b1f = __ldg(wk + 32);
        const uint2 b2f = __ldg(wk + 64);
        const uint2 b3f = __ldg(wk + 96);
        mma_f16(acc[0][0], A0, b0f);
        mma_f16(acc[0][1], A0, b1f);
        mma_f16(acc[0][2], A0, b2f);
        mma_f16(acc[0][3], A0, b3f);
        mma_f16(acc[1][0], A1, b0f);
        mma_f16(acc[1][1], A1, b1f);
        mma_f16(acc[1][2], A1, b2f);
        mma_f16(acc[1][3], A1, b3f);
    }
    __syncthreads();

    const int tl = tid >> 1, h2 = tid & 1;
    // h half (o 0..63): relu -> fp16
    if (warpN < 2) {
#pragma unroll
        for (int mf = 0; mf < 2; mf++)
#pragma unroll
            for (int nf = 0; nf < 4; nf++) {
                const int ro = warpM * 32 + mf * 16 + g;
                const int co = warpN * 36 + nf * 8 + tg * 2;
                smf[ro * 72 + co]           = acc[mf][nf][0];
                smf[ro * 72 + co + 1]       = acc[mf][nf][1];
                smf[(ro + 8) * 72 + co]     = acc[mf][nf][2];
                smf[(ro + 8) * 72 + co + 1] = acc[mf][nf][3];
            }
    }
    __syncthreads();
    if (tid < 128) {
        const float* crow = smf + tl * 72 + h2 * 36;
        __half* orow = hout + ((size_t)b * TLEN + t0 + tl) * 64 + h2 * 32;
#pragma unroll
        for (int j = 0; j < 8; j++) {
            const float4 bv = __ldg((const float4*)b0a + h2 * 8 + j);
            const float4 c = *(const float4*)(crow + j * 4);
            uint2 u;
            u.x = h2pack(fmaxf(c.x + bv.x, 0.f), fmaxf(c.y + bv.y, 0.f));
            u.y = h2pack(fmaxf(c.z + bv.z, 0.f), fmaxf(c.w + bv.w, 0.f));
            ((uint2*)orow)[j] = u;
        }
    }
    __syncthreads();
    // f half (o 64..127): no relu -> fp16
    if (warpN >= 2) {
#pragma unroll
        for (int mf = 0; mf < 2; mf++)
#pragma unroll
            for (int nf = 0; nf < 4; nf++) {
                const int ro = warpM * 32 + mf * 16 + g;
                const int co = (warpN - 2) * 36 + nf * 8 + tg * 2;
                smf[ro * 72 + co]           = acc[mf][nf][0];
                smf[ro * 72 + co + 1]       = acc[mf][nf][1];
                smf[(ro + 8) * 72 + co]     = acc[mf][nf][2];
                smf[(ro + 8) * 72 + co + 1] = acc[mf][nf][3];
            }
    }
    __syncthreads();
    if (tid < 128) {
        const float* crow = smf + tl * 72 + h2 * 36;
        __half* orow = fout + ((size_t)b * TLEN + t0 + tl) * 64 + h2 * 32;
#pragma unroll
        for (int j = 0; j < 8; j++) {
            const float4 bv = __ldg((const float4*)b0r + h2 * 8 + j);
            const float4 c = *(const float4*)(crow + j * 4);
            uint2 u;
            u.x = h2pack(c.x + bv.x, c.y + bv.y);
            u.y = h2pack(c.z + bv.z, c.w + bv.w);
            ((uint2*)orow)[j] = u;
        }
    }
}

// ===========================================================================
#define NCHAIN 4
#define BCH    (BATCH / NCHAIN)   // 32 batches per chain

extern "C" void kernel_launch(void* const* d_in, const int* in_sizes, int n_in,
                              void* d_out, int out_size)
{
    const float* x     = (const float*)d_in[0];
    const int*   ids   = (const int*)  d_in[1];
    const float* emb   = (const float*)d_in[2];
    const float* w0a   = (const float*)d_in[3];
    const float* b0a   = (const float*)d_in[4];
    const float* w0b   = (const float*)d_in[5];
    const float* b0b   = (const float*)d_in[6];
    const float* w0r   = (const float*)d_in[7];
    const float* b0r   = (const float*)d_in[8];
    const float* wa    = (const float*)d_in[9];
    const float* ba    = (const float*)d_in[10];
    const float* wb    = (const float*)d_in[11];
    const float* bb    = (const float*)d_in[12];
    const float* pet_w = (const float*)d_in[13];
    const float* pet_b = (const float*)d_in[14];
    const float* pck_w = (const float*)d_in[15];
    const float* pck_b = (const float*)d_in[16];
    const float* aet_w = (const float*)d_in[17];
    const float* aet_b = (const float*)d_in[18];
    float* out = (float*)d_out;

    __half *f, *h; uint2* wp;
    cudaGetSymbolAddress((void**)&f,  g_f);
    cudaGetSymbolAddress((void**)&h,  g_h);
    cudaGetSymbolAddress((void**)&wp, g_wp);

    static cudaStream_t s_aux[NCHAIN - 1] = {};
    static cudaEvent_t  ev_fork = nullptr;
    static cudaEvent_t  ev_join[NCHAIN - 1] = {};
    if (ev_fork == nullptr) {
        for (int i = 0; i < NCHAIN - 1; i++)
            cudaStreamCreateWithFlags(&s_aux[i], cudaStreamNonBlocking);
        cudaEventCreateWithFlags(&ev_fork, cudaEventDisableTiming);
        for (int i = 0; i < NCHAIN - 1; i++)
            cudaEventCreateWithFlags(&ev_join[i], cudaEventDisableTiming);
    }

    repack_kernel<<<(10 * 3072 + 255) / 256, 256>>>(w0b, wa, wb, w0a, w0r);
    cudaEventRecord(ev_fork, 0);
    for (int i = 0; i < NCHAIN - 1; i++)
        cudaStreamWaitEvent(s_aux[i], ev_fork, 0);

    const dim3 grid0(TLEN / 64, BCH);
    const dim3 grid(TLEN / 128, BCH);

#define MC(Dv, RS, HD, s, inp, outp, wset, bvec, b0v) \
    mconv_kernel<Dv, RS, HD><<<grid, 256, MCONV_SMEM, s>>>( \
        inp, outp, wp + (wset) * 3072, bvec, b0v, \
        pet_w, pet_b, pck_w, pck_b, aet_w, aet_b, out)

    for (int c = 0; c < NCHAIN; c++) {
        cudaStream_t s = (c == 0) ? (cudaStream_t)0 : s_aux[c - 1];
        const int b0 = c * BCH;

        conv0_kernel<<<grid0, 256, CONV0_SMEM, s>>>(x, ids, emb, wp + 9 * 3072,
                                                    b0a, b0r, h, f, b0);
        MC(1,  true,  false, s, h, f, 0, b0b,          b0);

        MC(2,  false, false, s, f, h, 1, ba + 0 * NCH, b0);
        MC(2,  true,  false, s, h, f, 5, bb + 0 * NCH, b0);

        MC(4,  false, false, s, f, h, 2, ba + 1 * NCH, b0);
        MC(4,  true,  false, s, h, f, 6, bb + 1 * NCH, b0);

        MC(8,  false, false, s, f, h, 3, ba + 2 * NCH, b0);
        MC(8,  true,  false, s, h, f, 7, bb + 2 * NCH, b0);

        MC(16, false, false, s, f, h, 4, ba + 3 * NCH, b0);
        MC(16, true,  true,  s, h, f, 8, bb + 3 * NCH, b0);   // fused head
    }
#undef MC

    for (int i = 0; i < NCHAIN - 1; i++) {
        cudaEventRecord(ev_join[i], s_aux[i]);
        cudaStreamWaitEvent((cudaStream_t)0, ev_join[i], 0);
    }
}